// round 5
// baseline (speedup 1.0000x reference)
#include <cuda_runtime.h>
#include <cuda_fp16.h>
#include <math.h>

#define BB 512
#define TT 512

// ---------------- device scratch (allocation-free rule) ----------------
__device__ __half g_gxh[(size_t)TT * BB * 512];   // gate pre-activations (fp16), reused per layer
__device__ float  g_h1[(size_t)BB * TT * 32];     // layer1 output
__device__ float  g_h2[(size_t)BB * TT * 48];     // layer2 output
__device__ float  g_Wt3[128 * 512];               // Whh3 transposed [k][col]

// ---------------- f32x2 helpers ----------------
__device__ __forceinline__ unsigned long long pk2(float a, float b) {
    unsigned long long r;
    asm("mov.b64 %0, {%1,%2};" : "=l"(r) : "f"(a), "f"(b));
    return r;
}
__device__ __forceinline__ void upk2(unsigned long long v, float& a, float& b) {
    asm("mov.b64 {%0,%1}, %2;" : "=f"(a), "=f"(b) : "l"(v));
}
__device__ __forceinline__ void fma2_(unsigned long long& d, unsigned long long a,
                                      unsigned long long b) {
    asm("fma.rn.f32x2 %0, %1, %2, %0;" : "+l"(d) : "l"(a), "l"(b));
}
__device__ __forceinline__ unsigned long long add2_(unsigned long long a,
                                                    unsigned long long b) {
    unsigned long long r;
    asm("add.rn.f32x2 %0, %1, %2;" : "=l"(r) : "l"(a), "l"(b));
    return r;
}
__device__ __forceinline__ float sig_(float x) { return 1.0f / (1.0f + __expf(-x)); }
__device__ __forceinline__ float th_(float x) { return 1.0f - 2.0f / (__expf(2.0f * x) + 1.0f); }

// ---------------------------------------------------------------------------
// Input projection: smem x-tile stored transposed in row-quads:
//   xs4[k][rq] = (x[rq*4+0][k], x[rq*4+1][k], x[rq*4+2][k], x[rq*4+3][k]).
// One broadcast LDS.128 (read as ulonglong2) = the two packed f32x2
// multiplicands -> zero packing movs in the inner loop.
// CPT cols per thread (cols tid + j*NT), weights pre-packed (w,w).
// ---------------------------------------------------------------------------
template <int D, int NT, int CPT, int MT>
__global__ void __launch_bounds__(NT)
lstm_projQ(const float* __restrict__ x, const float* __restrict__ Wih,
           const float* __restrict__ bih, const float* __restrict__ bhh,
           __half* __restrict__ gx)
{
    constexpr int NTOT = NT * CPT;
    const int tid = threadIdx.x;

    unsigned long long w2[CPT][D];
    unsigned long long b2[CPT];
#pragma unroll
    for (int j = 0; j < CPT; j++) {
        int col = tid + j * NT;
#pragma unroll
        for (int k = 0; k < D; k++) {
            float w = __ldg(&Wih[col * D + k]);
            w2[j][k] = pk2(w, w);
        }
        float bs = __ldg(&bih[col]) + __ldg(&bhh[col]);
        b2[j] = pk2(bs, bs);
    }

    __shared__ __align__(16) float xs4[D][MT / 4][4];
    const int ntiles = (BB * TT) / MT;

#pragma unroll 1
    for (int tile = blockIdx.x; tile < ntiles; tile += gridDim.x) {
        __syncthreads();
#pragma unroll 1
        for (int i = tid; i < MT * (D / 4); i += NT) {
            int r = i / (D / 4), k4 = i % (D / 4);
            float4 v = ((const float4*)x)[(size_t)tile * (MT * D / 4) + i];
            int rq = r >> 2, rl = r & 3;
            xs4[4 * k4 + 0][rq][rl] = v.x;
            xs4[4 * k4 + 1][rq][rl] = v.y;
            xs4[4 * k4 + 2][rq][rl] = v.z;
            xs4[4 * k4 + 3][rq][rl] = v.w;
        }
        __syncthreads();

#pragma unroll 1
        for (int rq = 0; rq < MT / 4; rq++) {
            unsigned long long a01[CPT][2], a23[CPT][2];
#pragma unroll
            for (int j = 0; j < CPT; j++) {
                a01[j][0] = b2[j]; a01[j][1] = 0ull;
                a23[j][0] = b2[j]; a23[j][1] = 0ull;
            }
#pragma unroll
            for (int k = 0; k < D; k++) {
                ulonglong2 v = *(const ulonglong2*)&xs4[k][rq][0];
#pragma unroll
                for (int j = 0; j < CPT; j++) {
                    fma2_(a01[j][k & 1], w2[j][k], v.x);
                    fma2_(a23[j][k & 1], w2[j][k], v.y);
                }
            }
            int m = tile * MT + rq * 4;
            int b = m >> 9, t = m & 511;          // rows -> t..t+3, same b
            size_t base = ((size_t)t * BB + b) * NTOT;
            const size_t ts = (size_t)BB * NTOT;
#pragma unroll
            for (int j = 0; j < CPT; j++) {
                float g0, g1, g2v, g3v;
                upk2(add2_(a01[j][0], a01[j][1]), g0, g1);
                upk2(add2_(a23[j][0], a23[j][1]), g2v, g3v);
                int col = tid + j * NT;
                gx[base + col]          = __float2half(g0);
                gx[base + ts + col]     = __float2half(g1);
                gx[base + 2 * ts + col] = __float2half(g2v);
                gx[base + 3 * ts + col] = __float2half(g3v);
            }
        }
    }
}

// ---------------------------------------------------------------------------
// Small-layer recurrence (L1: H=32, L2: H=48), fp16 gx, depth-2 prefetch.
// ---------------------------------------------------------------------------
template <int H>
__global__ void __launch_bounds__(4 * H)
lstm_recur_small(const __half* __restrict__ gx,  // [T][B][4H] fp16
                 const float* __restrict__ Whh,  // [4H][H]
                 float* __restrict__ out)        // [B][T][H]
{
    constexpr int G = 4 * H;
    const int col = threadIdx.x;
    const int b0 = blockIdx.x * 2;

    unsigned long long wh2[H];
#pragma unroll
    for (int k = 0; k < H; k++) {
        float w = __ldg(&Whh[col * H + k]);
        wh2[k] = pk2(w, w);
    }

    __shared__ unsigned long long h2[H];
    __shared__ unsigned long long g2[G];
    if (col < H) h2[col] = 0ull;

    const int erow = col & 1, ecol = col >> 1;
    float c = 0.f;

    const __half* gbase = gx + (size_t)b0 * G + col;
    const size_t tstride = (size_t)BB * G;

    __half A0 = gbase[0], A1 = gbase[G];
    __half B0 = gbase[tstride], B1 = gbase[tstride + G];
    __syncthreads();

    for (int t = 0; t < TT; t++) {
        __half C0 = __float2half(0.f), C1 = C0;
        if (t + 2 < TT) {
            const __half* gp = gbase + (size_t)(t + 2) * tstride;
            C0 = gp[0]; C1 = gp[G];
        }
        unsigned long long a0 = 0ull, a1 = 0ull, a2 = 0ull, a3 = 0ull;
#pragma unroll
        for (int k = 0; k < H; k += 4) {
            fma2_(a0, wh2[k + 0], h2[k + 0]);
            fma2_(a1, wh2[k + 1], h2[k + 1]);
            fma2_(a2, wh2[k + 2], h2[k + 2]);
            fma2_(a3, wh2[k + 3], h2[k + 3]);
        }
        g2[col] = add2_(add2_(add2_(a0, a1), add2_(a2, a3)),
                        pk2(__half2float(A0), __half2float(A1)));
        A0 = B0; A1 = B1; B0 = C0; B1 = C1;
        __syncthreads();

        if (col < 2 * H) {
            const float* gf = (const float*)g2;
            float gi = gf[2 * ecol + erow];
            float gF = gf[2 * (H + ecol) + erow];
            float gg = gf[2 * (2 * H + ecol) + erow];
            float go = gf[2 * (3 * H + ecol) + erow];
            c = sig_(gF) * c + sig_(gi) * th_(gg);
            float h = sig_(go) * th_(c);
            ((float*)h2)[2 * ecol + erow] = h;
            out[((size_t)(b0 + erow) * TT + t) * H + ecol] = h;
        }
        __syncthreads();
    }
}

// ---------------------------------------------------------------------------
// Layer-3 recurrence: smem weights packed [kpair][tid] float4 (2 k-rows x
// 2 cols per LDS.128); register tail pre-duplicated u64 (no per-step movs).
// KSM=104 k-rows in smem (52 pairs), KRG=24 in registers.
// ---------------------------------------------------------------------------
#define KSM 104
#define KPAIRS (KSM / 2)
#define KRG (128 - KSM)
#define SMEM_BIG (KPAIRS * 256 * 16 + 128 * 16 + 512 * 16)   // 223,232 B

__global__ void __launch_bounds__(256)
lstm_recur_big(const __half* __restrict__ gx,  // [T][B][512] fp16
               const float* __restrict__ Wt,   // [128][512] transposed Whh3
               float* __restrict__ out,        // [B][T][128]
               float* __restrict__ hn)         // [B][128]
{
    extern __shared__ char sraw[];
    float4* Wsm2 = (float4*)sraw;                                          // [KPAIRS][256]
    unsigned long long* hp = (unsigned long long*)(sraw + KPAIRS * 256 * 16);         // [128][2]
    unsigned long long* g4 = (unsigned long long*)(sraw + KPAIRS * 256 * 16 + 2048);  // [512][2]

    const int tid = threadIdx.x;
    const int b0 = blockIdx.x * 4;
    const int c0 = tid * 2;

    // smem weights: [kpair][tid] = {Wt[2kp][c0], Wt[2kp][c0+1], Wt[2kp+1][c0], Wt[2kp+1][c0+1]}
    for (int kp = 0; kp < KPAIRS; kp++) {
        float2 wa = *(const float2*)(Wt + (size_t)(2 * kp) * 512 + c0);
        float2 wb = *(const float2*)(Wt + (size_t)(2 * kp + 1) * 512 + c0);
        Wsm2[kp * 256 + tid] = make_float4(wa.x, wa.y, wb.x, wb.y);
    }
    // register tail: pre-duplicated packed weights
    unsigned long long wgp0[KRG], wgp1[KRG];
#pragma unroll
    for (int j = 0; j < KRG; j++) {
        float2 w = *(const float2*)(Wt + (size_t)(KSM + j) * 512 + c0);
        wgp0[j] = pk2(w.x, w.x);
        wgp1[j] = pk2(w.y, w.y);
    }

    hp[tid] = 0ull;

    const int ecol = tid & 127, erp = tid >> 7;
    float cA = 0.f, cB = 0.f;

    const __half2* gb = (const __half2*)(gx + (size_t)b0 * 512 + c0);
    const size_t tstride = (size_t)BB * 256;   // in half2 units

    __half2 pA0 = gb[0], pA1 = gb[256], pA2 = gb[512], pA3 = gb[768];
    __half2 pB0 = gb[tstride + 0], pB1 = gb[tstride + 256],
            pB2 = gb[tstride + 512], pB3 = gb[tstride + 768];
    __syncthreads();

    const ulonglong2* hp2 = (const ulonglong2*)hp;

    for (int t = 0; t < TT; t++) {
        __half2 pC0, pC1, pC2, pC3;
        pC0 = pC1 = pC2 = pC3 = __float2half2_rn(0.f);
        if (t + 2 < TT) {
            const __half2* gp = gb + (size_t)(t + 2) * tstride;
            pC0 = gp[0]; pC1 = gp[256]; pC2 = gp[512]; pC3 = gp[768];
        }

        unsigned long long A00 = 0, A01 = 0, A10 = 0, A11 = 0;
        unsigned long long B00 = 0, B01 = 0, B10 = 0, B11 = 0;

#pragma unroll 4
        for (int kp = 0; kp < KPAIRS; kp++) {
            float4 w = Wsm2[kp * 256 + tid];
            ulonglong2 h0 = hp2[2 * kp];
            ulonglong2 h1 = hp2[2 * kp + 1];
            unsigned long long w00 = pk2(w.x, w.x), w01 = pk2(w.y, w.y);
            unsigned long long w10 = pk2(w.z, w.z), w11 = pk2(w.w, w.w);
            fma2_(A00, w00, h0.x); fma2_(A01, w00, h0.y);
            fma2_(A10, w01, h0.x); fma2_(A11, w01, h0.y);
            fma2_(B00, w10, h1.x); fma2_(B01, w10, h1.y);
            fma2_(B10, w11, h1.x); fma2_(B11, w11, h1.y);
        }
#pragma unroll
        for (int j = 0; j < KRG; j++) {
            ulonglong2 h = hp2[KSM + j];
            if (j & 1) { fma2_(B00, wgp0[j], h.x); fma2_(B01, wgp0[j], h.y);
                         fma2_(B10, wgp1[j], h.x); fma2_(B11, wgp1[j], h.y); }
            else       { fma2_(A00, wgp0[j], h.x); fma2_(A01, wgp0[j], h.y);
                         fma2_(A10, wgp1[j], h.x); fma2_(A11, wgp1[j], h.y); }
        }

        float2 f0 = __half22float2(pA0), f1 = __half22float2(pA1);
        float2 f2 = __half22float2(pA2), f3 = __half22float2(pA3);
        pA0 = pB0; pA1 = pB1; pA2 = pB2; pA3 = pB3;
        pB0 = pC0; pB1 = pC1; pB2 = pC2; pB3 = pC3;

        ulonglong2 r0, r1;
        r0.x = add2_(add2_(A00, B00), pk2(f0.x, f1.x));
        r0.y = add2_(add2_(A01, B01), pk2(f2.x, f3.x));
        r1.x = add2_(add2_(A10, B10), pk2(f0.y, f1.y));
        r1.y = add2_(add2_(A11, B11), pk2(f2.y, f3.y));
        ((ulonglong2*)g4)[c0]     = r0;
        ((ulonglong2*)g4)[c0 + 1] = r1;
        __syncthreads();

        {
            const float2* gf2 = (const float2*)g4;
            float2 gi = gf2[(ecol      ) * 2 + erp];
            float2 gF = gf2[(ecol + 128) * 2 + erp];
            float2 gg = gf2[(ecol + 256) * 2 + erp];
            float2 go = gf2[(ecol + 384) * 2 + erp];
            cA = sig_(gF.x) * cA + sig_(gi.x) * th_(gg.x);
            cB = sig_(gF.y) * cB + sig_(gi.y) * th_(gg.y);
            float h0 = sig_(go.x) * th_(cA);
            float h1 = sig_(go.y) * th_(cB);
            hp[ecol * 2 + erp] = pk2(h0, h1);
            out[((size_t)(b0 + 2 * erp) * TT + t) * 128 + ecol] = h0;
            out[((size_t)(b0 + 2 * erp + 1) * TT + t) * 128 + ecol] = h1;
            if (t == TT - 1) {
                hn[(size_t)(b0 + 2 * erp) * 128 + ecol] = h0;
                hn[(size_t)(b0 + 2 * erp + 1) * 128 + ecol] = h1;
            }
        }
        __syncthreads();
    }
}

// ---------------------------------------------------------------------------
__global__ void transposeW3(const float* __restrict__ Whh, float* __restrict__ Wt)
{
    int i = blockIdx.x * 256 + threadIdx.x;
    if (i < 128 * 512) {
        int k = i >> 9, col = i & 511;
        Wt[i] = Whh[col * 128 + k];
    }
}

// ---------------------------------------------------------------------------
extern "C" void kernel_launch(void* const* d_in, const int* in_sizes, int n_in,
                              void* d_out, int out_size)
{
    const float* z    = (const float*)d_in[0];
    const float* Wih1 = (const float*)d_in[1];
    const float* Whh1 = (const float*)d_in[2];
    const float* bih1 = (const float*)d_in[3];
    const float* bhh1 = (const float*)d_in[4];
    const float* Wih2 = (const float*)d_in[5];
    const float* Whh2 = (const float*)d_in[6];
    const float* bih2 = (const float*)d_in[7];
    const float* bhh2 = (const float*)d_in[8];
    const float* Wih3 = (const float*)d_in[9];
    const float* Whh3 = (const float*)d_in[10];
    const float* bih3 = (const float*)d_in[11];
    const float* bhh3 = (const float*)d_in[12];

    float* dec = (float*)d_out;                        // [B,T,128]
    float* hn  = dec + (size_t)BB * TT * 128;          // [1,B,128]

    __half* gx;
    float *h1, *h2, *Wt3;
    cudaGetSymbolAddress((void**)&gx, g_gxh);
    cudaGetSymbolAddress((void**)&h1, g_h1);
    cudaGetSymbolAddress((void**)&h2, g_h2);
    cudaGetSymbolAddress((void**)&Wt3, g_Wt3);

    cudaFuncSetAttribute(lstm_recur_big,
                         cudaFuncAttributeMaxDynamicSharedMemorySize, SMEM_BIG);

    transposeW3<<<256, 256>>>(Whh3, Wt3);

    // Layer 1: 64 -> 32   (D=64, NT=128, CPT=1, MT=64)
    lstm_projQ<64, 128, 1, 64><<<4096, 128>>>(z, Wih1, bih1, bhh1, gx);
    lstm_recur_small<32><<<BB / 2, 128>>>(gx, Whh1, h1);

    // Layer 2: 32 -> 48   (D=32, NT=96, CPT=2, MT=64)
    lstm_projQ<32, 96, 2, 64><<<4096, 96>>>(h1, Wih2, bih2, bhh2, gx);
    lstm_recur_small<48><<<BB / 2, 192>>>(gx, Whh2, h2);

    // Layer 3: 48 -> 128  (D=48, NT=512, CPT=1, MT=64)
    lstm_projQ<48, 512, 1, 64><<<4096, 512>>>(h2, Wih3, bih3, bhh3, gx);
    lstm_recur_big<<<BB / 4, 256, SMEM_BIG>>>(gx, Wt3, dec, hn);
}